// round 9
// baseline (speedup 1.0000x reference)
#include <cuda_runtime.h>
#include <cuda_pipeline.h>

#define THREADS 256
#define CPB     128
#define PF      (CPB * 30)    // 3840 floats P per chunk
#define TF      (CPB * 25)    // 3200 floats T per chunk
#define MAX_PART 2048

__device__ float g_partials[MAX_PART];
__device__ unsigned int g_count = 0;   // wraps to 0 each replay via atomicInc

__global__ __launch_bounds__(THREADS) void yolo_loss_kernel(
    const float* __restrict__ pred,   // [n_cells, 30]
    const float* __restrict__ targ,   // [n_cells, 25]
    long n_cells,
    long n_chunks,
    float* __restrict__ out)
{
    __shared__ __align__(16) float sT[2][TF];       // 2 x 12800 B
    __shared__ float sC1[CPB], sC2[CPB];            // published P4 / P9 per cell

    const int tid = threadIdx.x;
    const long grid = gridDim.x;

    auto stageT = [&](int buf, long ch) {
        if (ch < n_chunks) {
            long cb = ch * CPB;
            int cells = (int)min((long)CPB, n_cells - cb);
            int n4 = (cells * 25) >> 2;
            const float4* g4 = reinterpret_cast<const float4*>(targ + cb * 25); // 12800B*ch: aligned
            float4* s4 = reinterpret_cast<float4*>(sT[buf]);
            for (int i = tid; i < n4; i += THREADS)
                __pipeline_memcpy_async(&s4[i], &g4[i], 16);
            for (int i = (n4 << 2) + tid; i < cells * 25; i += THREADS)
                __pipeline_memcpy_async(&sT[buf][i], &targ[cb * 25 + i], 4);
        }
        __pipeline_commit();
    };

    float acc = 0.0f;
    long chunk = blockIdx.x;
    stageT(0, chunk);
    int it = 0;

    while (chunk < n_chunks) {
        const long cb = chunk * CPB;
        const int cells = (int)min((long)CPB, n_cells - cb);
        const int nelem = cells * 30;
        const int cur = it & 1;

        // ---- dense coalesced P load: 4 float4 per thread, straight to regs ----
        float pr[16];
        {
            const float4* gp = reinterpret_cast<const float4*>(pred + cb * 30); // 15360B*ch: aligned
            #pragma unroll
            for (int q = 0; q < 4; ++q) {
                int f4 = tid + q * THREADS;
                float4 v = (f4 * 4 < nelem) ? __ldg(gp + f4) : make_float4(0, 0, 0, 0);
                pr[q * 4 + 0] = v.x; pr[q * 4 + 1] = v.y;
                pr[q * 4 + 2] = v.z; pr[q * 4 + 3] = v.w;
            }
        }

        // ---- prefetch next chunk's T while P is in flight ----
        stageT(cur ^ 1, chunk + grid);
        __pipeline_wait_prior(1);        // T(chunk) resident

        // ---- publish conf fields (P4, P9) to smem ----
        #pragma unroll
        for (int q = 0; q < 4; ++q) {
            int e = (tid + q * THREADS) * 4;
            #pragma unroll
            for (int j = 0; j < 4; ++j, ++e) {
                if (e < nelem) {
                    int c = e / 30;
                    int f = e - c * 30;
                    if (f == 4) sC1[c] = pr[q * 4 + j];
                    else if (f == 9) sC2[c] = pr[q * 4 + j];
                }
            }
        }
        __syncthreads();

        // ---- element-local terms ----
        const float* T = sT[cur];
        #pragma unroll
        for (int q = 0; q < 4; ++q) {
            int e = (tid + q * THREADS) * 4;
            #pragma unroll
            for (int j = 0; j < 4; ++j, ++e) {
                if (e >= nelem) continue;
                int c = e / 30;
                int f = e - c * 30;
                float p = pr[q * 4 + j];
                float tc = T[c * 25 + 4];
                bool present = (tc == 1.0f);
                bool r1 = (sC1[c] > sC2[c]);

                float term = 0.0f;
                if (f == 4) {
                    term = present ? (r1 ? (p - tc) * (p - tc) : 0.0f)
                                   : 0.5f * p * p;
                } else if (f == 9) {
                    term = present ? (!r1 ? (p - tc) * (p - tc) : 0.0f)
                                   : 0.5f * p * p;
                } else if (f >= 10) {
                    if (present) {
                        float d = p - T[c * 25 + (f - 5)];
                        term = d * d;
                    }
                } else {                         // box fields 0..3 / 5..8
                    bool mine = (f < 4) ? r1 : !r1;
                    if (present && mine) {
                        int g = (f < 4) ? f : f - 5;
                        float tv = T[c * 25 + g];
                        float d = (g < 2) ? (p - tv) : (sqrtf(p) - sqrtf(tv));
                        term = 5.0f * d * d;
                    }
                }
                acc += term;
            }
        }
        __syncthreads();                 // conf table + T slot reuse safety

        chunk += grid;
        ++it;
    }

    // ---- block reduction (8 warps) ----
    #pragma unroll
    for (int off = 16; off > 0; off >>= 1)
        acc += __shfl_xor_sync(0xFFFFFFFFu, acc, off);

    __shared__ float wsum[THREADS / 32];
    const int wid = tid >> 5, lid = tid & 31;
    if (lid == 0) wsum[wid] = acc;
    __syncthreads();

    __shared__ int s_last;
    if (tid == 0) {
        float b = 0.0f;
        #pragma unroll
        for (int i = 0; i < THREADS / 32; ++i) b += wsum[i];
        g_partials[blockIdx.x] = b;
        __threadfence();
        unsigned old = atomicInc(&g_count, gridDim.x - 1);
        s_last = (old == gridDim.x - 1) ? 1 : 0;
    }
    __syncthreads();

    if (s_last) {
        __threadfence();
        double d = 0.0;
        for (int i = tid; i < (int)gridDim.x; i += THREADS)
            d += (double)__ldcg(&g_partials[i]);
        #pragma unroll
        for (int off = 16; off > 0; off >>= 1)
            d += __shfl_xor_sync(0xFFFFFFFFu, d, off);
        __shared__ double dsum[THREADS / 32];
        if (lid == 0) dsum[wid] = d;
        __syncthreads();
        if (tid == 0) {
            double s = 0.0;
            #pragma unroll
            for (int i = 0; i < THREADS / 32; ++i) s += dsum[i];
            out[0] = (float)s;
        }
    }
}

extern "C" void kernel_launch(void* const* d_in, const int* in_sizes, int n_in,
                              void* d_out, int out_size) {
    const float* pred = (const float*)d_in[0];   // [B, 1470]
    const float* targ = (const float*)d_in[1];   // [B, 1225]
    float* out = (float*)d_out;

    long B = (long)in_sizes[0] / 1470;
    long n_cells = B * 49;
    long n_chunks = (n_cells + CPB - 1) / CPB;

    long blocks = 148L * 4;                      // ~27.8 KB smem, ~45 regs -> 4 blocks/SM
    if (blocks > n_chunks) blocks = n_chunks;
    if (blocks > MAX_PART) blocks = MAX_PART;

    yolo_loss_kernel<<<(unsigned)blocks, THREADS>>>(pred, targ, n_cells, n_chunks, out);
}

// round 10
// speedup vs baseline: 3.5944x; 3.5944x over previous
#include <cuda_runtime.h>

#define THREADS 128
#define CPB     128
#define PF4     960          // P float4s per chunk (128*30/4)
#define TF4     800          // T float4s per chunk (128*25/4)
#define NF4     (PF4 + TF4)  // 1760 float4s per chunk
#define LD_PER_T 14          // ceil(1760/128)
#define MAX_PART 2048

__device__ float g_partials[MAX_PART];
__device__ unsigned int g_count = 0;   // wraps to 0 each replay via atomicInc

__device__ __forceinline__ float cell_loss(const float* P, const float* T) {
    float c1 = P[4], c2 = P[9], c = T[4];
    bool present = (c == 1.0f);
    bool r1 = (c1 > c2);
    if (present) {
        float dobj = (r1 ? c1 : c2) - c;
        float loss = dobj * dobj;
        float cls = 0.0f;
        #pragma unroll
        for (int i = 0; i < 20; ++i) {
            float d = P[10 + i] - T[5 + i];
            cls = fmaf(d, d, cls);
        }
        int o = r1 ? 0 : 5;
        float box = 0.0f;
        #pragma unroll
        for (int i = 0; i < 2; ++i) {
            float d = P[o + i] - T[i];
            box = fmaf(d, d, box);
        }
        #pragma unroll
        for (int i = 0; i < 2; ++i) {
            float d = sqrtf(P[o + 2 + i]) - sqrtf(T[2 + i]);
            box = fmaf(d, d, box);
        }
        return loss + cls + 5.0f * box;
    }
    return 0.5f * fmaf(c1, c1, c2 * c2);
}

__global__ __launch_bounds__(THREADS, 6) void yolo_loss_kernel(
    const float* __restrict__ pred,   // [n_cells, 30]
    const float* __restrict__ targ,   // [n_cells, 25]
    long n_cells,
    long n_full,                      // full 128-cell chunks
    float* __restrict__ out)
{
    __shared__ __align__(16) float4 sm4[NF4];   // 28160 B: P [0,960), T [960,1760)
    float* sm = reinterpret_cast<float*>(sm4);

    const int tid = threadIdx.x;
    const long grid = gridDim.x;
    const float4* p4 = reinterpret_cast<const float4*>(pred);
    const float4* t4 = reinterpret_cast<const float4*>(targ);

    // register-buffered dense coalesced load of one full chunk
    float4 v[LD_PER_T];
    auto load_chunk = [&](long c) {
        const long pb = c * PF4, tb = c * TF4;
        #pragma unroll
        for (int j = 0; j < LD_PER_T; ++j) {
            int i = j * THREADS + tid;
            if (j == LD_PER_T - 1 && i >= NF4) continue;     // tid>=96 on last j
            v[j] = (i < PF4) ? __ldcs(p4 + pb + i)           // warp-uniform branch
                             : __ldcs(t4 + tb + (i - PF4));
        }
    };

    float acc = 0.0f;
    long chunk = blockIdx.x;
    if (chunk < n_full) load_chunk(chunk);       // prologue

    while (chunk < n_full) {
        // ---- spill registers -> smem (transpose point) ----
        #pragma unroll
        for (int j = 0; j < LD_PER_T; ++j) {
            int i = j * THREADS + tid;
            if (j == LD_PER_T - 1 && i >= NF4) continue;
            sm4[i] = v[j];
        }
        __syncthreads();                         // chunk resident in smem

        // ---- issue next chunk's loads (overlap with compute below) ----
        long next = chunk + grid;
        if (next < n_full) load_chunk(next);

        // ---- per-cell compute from smem (proven R4 consumer) ----
        acc += cell_loss(sm + tid * 30, sm + PF4 * 4 + tid * 25);

        __syncthreads();                         // all reads done before next STS
        chunk = next;
    }

    // ---- ragged tail cells: block 0, direct loads ----
    if (blockIdx.x == 0) {
        for (long cell = n_full * CPB + tid; cell < n_cells; cell += THREADS) {
            float Pl[30], Tl[25];
            #pragma unroll
            for (int i = 0; i < 30; ++i) Pl[i] = __ldg(pred + cell * 30 + i);
            #pragma unroll
            for (int i = 0; i < 25; ++i) Tl[i] = __ldg(targ + cell * 25 + i);
            acc += cell_loss(Pl, Tl);
        }
    }

    // ---- block reduction ----
    #pragma unroll
    for (int off = 16; off > 0; off >>= 1)
        acc += __shfl_xor_sync(0xFFFFFFFFu, acc, off);

    __shared__ float wsum[THREADS / 32];
    const int wid = tid >> 5, lid = tid & 31;
    if (lid == 0) wsum[wid] = acc;
    __syncthreads();

    __shared__ int s_last;
    if (tid == 0) {
        g_partials[blockIdx.x] = wsum[0] + wsum[1] + wsum[2] + wsum[3];
        __threadfence();
        unsigned old = atomicInc(&g_count, gridDim.x - 1);
        s_last = (old == gridDim.x - 1) ? 1 : 0;
    }
    __syncthreads();

    if (s_last) {
        __threadfence();
        double d = 0.0;
        for (int i = tid; i < (int)gridDim.x; i += THREADS)
            d += (double)__ldcg(&g_partials[i]);
        #pragma unroll
        for (int off = 16; off > 0; off >>= 1)
            d += __shfl_xor_sync(0xFFFFFFFFu, d, off);
        __shared__ double dsum[THREADS / 32];
        if (lid == 0) dsum[wid] = d;
        __syncthreads();
        if (tid == 0)
            out[0] = (float)(dsum[0] + dsum[1] + dsum[2] + dsum[3]);
    }
}

extern "C" void kernel_launch(void* const* d_in, const int* in_sizes, int n_in,
                              void* d_out, int out_size) {
    const float* pred = (const float*)d_in[0];   // [B, 1470]
    const float* targ = (const float*)d_in[1];   // [B, 1225]
    float* out = (float*)d_out;

    long B = (long)in_sizes[0] / 1470;
    long n_cells = B * 49;
    long n_full = n_cells / CPB;                 // 6272 for B=16384

    long blocks = 148L * 6;                      // 28.2 KB smem, <=85 regs -> 6 blocks/SM
    if (blocks > n_full) blocks = (n_full > 0) ? n_full : 1;
    if (blocks > MAX_PART) blocks = MAX_PART;

    yolo_loss_kernel<<<(unsigned)blocks, THREADS>>>(pred, targ, n_cells, n_full, out);
}

// round 11
// speedup vs baseline: 3.8470x; 1.0703x over previous
#include <cuda_runtime.h>
#include <cstdint>

#define THREADS 128
#define CPB     128
#define STAGES  4
#define PRED_F  (CPB * 30)        // 3840 floats
#define TARG_F  (CPB * 25)        // 3200 floats
#define PF4     (PRED_F / 4)      // 960 float4
#define TF4     (TARG_F / 4)      // 800 float4
#define MAX_RES 296               // 2 blocks/SM x 148 SMs
#define MAX_PART 2048

__device__ float g_partials[MAX_PART];
__device__ unsigned int g_count = 0;   // wraps to 0 each replay via atomicInc

__device__ __forceinline__ void cp16_l2(unsigned smem_addr, const void* gptr) {
    asm volatile("cp.async.cg.shared.global.L2::256B [%0], [%1], 16;"
                 :: "r"(smem_addr), "l"(gptr) : "memory");
}
__device__ __forceinline__ void cp_commit() {
    asm volatile("cp.async.commit_group;" ::: "memory");
}
template <int N>
__device__ __forceinline__ void cp_wait() {
    asm volatile("cp.async.wait_group %0;" :: "n"(N) : "memory");
}

__device__ __forceinline__ float cell_loss(const float* P, const float* T) {
    float c1 = P[4], c2 = P[9], c = T[4];
    bool present = (c == 1.0f);
    bool r1 = (c1 > c2);
    if (present) {
        float dobj = (r1 ? c1 : c2) - c;
        float loss = dobj * dobj;
        float cls = 0.0f;
        #pragma unroll
        for (int i = 0; i < 20; ++i) {
            float d = P[10 + i] - T[5 + i];
            cls = fmaf(d, d, cls);
        }
        int o = r1 ? 0 : 5;
        float box = 0.0f;
        #pragma unroll
        for (int i = 0; i < 2; ++i) {
            float d = P[o + i] - T[i];
            box = fmaf(d, d, box);
        }
        #pragma unroll
        for (int i = 0; i < 2; ++i) {
            float d = sqrtf(P[o + 2 + i]) - sqrtf(T[2 + i]);
            box = fmaf(d, d, box);
        }
        return loss + cls + 5.0f * box;
    }
    return 0.5f * fmaf(c1, c1, c2 * c2);
}

__global__ __launch_bounds__(THREADS) void yolo_loss_kernel(
    const float* __restrict__ pred,   // [n_cells, 30]
    const float* __restrict__ targ,   // [n_cells, 25]
    long n_cells,
    long n_full,                      // full 128-cell chunks
    float* __restrict__ out)
{
    __shared__ __align__(16) float sP[STAGES][PRED_F];   // 4 x 15360 B
    __shared__ __align__(16) float sT[STAGES][TARG_F];   // 4 x 12800 B

    const int tid = threadIdx.x;
    const long grid = gridDim.x;

    const unsigned spb = (unsigned)__cvta_generic_to_shared(&sP[0][0]);
    const unsigned stb = (unsigned)__cvta_generic_to_shared(&sT[0][0]);

    // stage one full chunk into slot (all 128 threads; exact float4 counts)
    auto stage = [&](int slot, long ch) {
        if (ch < n_full) {
            const float4* gp = reinterpret_cast<const float4*>(pred) + ch * PF4;
            const float4* gt = reinterpret_cast<const float4*>(targ) + ch * TF4;
            unsigned sp = spb + (unsigned)slot * (PRED_F * 4);
            unsigned st = stb + (unsigned)slot * (TARG_F * 4);
            #pragma unroll
            for (int j = 0; j < PF4 / THREADS + 1; ++j) {      // 960/128 = 7.5
                int i = j * THREADS + tid;
                if (i < PF4) cp16_l2(sp + i * 16, gp + i);
            }
            #pragma unroll
            for (int j = 0; j < TF4 / THREADS + 1; ++j) {      // 800/128 = 6.25
                int i = j * THREADS + tid;
                if (i < TF4) cp16_l2(st + i * 16, gt + i);
            }
        }
        cp_commit();   // uniform group accounting
    };

    // ---- prologue ----
    #pragma unroll
    for (int s = 0; s < STAGES - 1; ++s)
        stage(s, (long)blockIdx.x + (long)s * grid);

    float acc = 0.0f;
    long chunk = blockIdx.x;
    int it = 0;

    while (chunk < n_full) {
        cp_wait<STAGES - 2>();           // chunk 'it' resident
        __syncthreads();

        int slot = it & (STAGES - 1);
        acc += cell_loss(sP[slot] + tid * 30, sT[slot] + tid * 25);

        // refill slot (it+STAGES-1)%STAGES — its old contents (chunk it-1)
        // were consumed before this iteration's barrier
        stage((it + STAGES - 1) & (STAGES - 1), chunk + (long)(STAGES - 1) * grid);

        chunk += grid;
        ++it;
    }

    // ---- ragged tail: block 0, direct loads ----
    if (blockIdx.x == 0) {
        for (long cell = n_full * CPB + tid; cell < n_cells; cell += THREADS) {
            float Pl[30], Tl[25];
            #pragma unroll
            for (int i = 0; i < 30; ++i) Pl[i] = __ldg(pred + cell * 30 + i);
            #pragma unroll
            for (int i = 0; i < 25; ++i) Tl[i] = __ldg(targ + cell * 25 + i);
            acc += cell_loss(Pl, Tl);
        }
    }

    // ---- block reduction ----
    #pragma unroll
    for (int off = 16; off > 0; off >>= 1)
        acc += __shfl_xor_sync(0xFFFFFFFFu, acc, off);

    __shared__ float wsum[THREADS / 32];
    const int wid = tid >> 5, lid = tid & 31;
    if (lid == 0) wsum[wid] = acc;
    __syncthreads();

    __shared__ int s_last;
    if (tid == 0) {
        g_partials[blockIdx.x] = wsum[0] + wsum[1] + wsum[2] + wsum[3];
        __threadfence();
        unsigned old = atomicInc(&g_count, gridDim.x - 1);
        s_last = (old == gridDim.x - 1) ? 1 : 0;
    }
    __syncthreads();

    if (s_last) {
        __threadfence();
        double d = 0.0;
        for (int i = tid; i < (int)gridDim.x; i += THREADS)
            d += (double)__ldcg(&g_partials[i]);
        #pragma unroll
        for (int off = 16; off > 0; off >>= 1)
            d += __shfl_xor_sync(0xFFFFFFFFu, d, off);
        __shared__ double dsum[THREADS / 32];
        if (lid == 0) dsum[wid] = d;
        __syncthreads();
        if (tid == 0)
            out[0] = (float)(dsum[0] + dsum[1] + dsum[2] + dsum[3]);
    }
}

extern "C" void kernel_launch(void* const* d_in, const int* in_sizes, int n_in,
                              void* d_out, int out_size) {
    const float* pred = (const float*)d_in[0];   // [B, 1470]
    const float* targ = (const float*)d_in[1];   // [B, 1225]
    float* out = (float*)d_out;

    long B = (long)in_sizes[0] / 1470;
    long n_cells = B * 49;
    long n_full = n_cells / CPB;                 // 6272 for B=16384

    // balanced grid: all blocks get ceil or ceil-1 chunks with minimal spread
    long blocks;
    if (n_full <= 0) {
        blocks = 1;
    } else {
        long k = (n_full + MAX_RES - 1) / MAX_RES;   // chunks per block (ceil)
        blocks = (n_full + k - 1) / k;               // 286 for 6272
    }
    if (blocks > MAX_PART) blocks = MAX_PART;

    yolo_loss_kernel<<<(unsigned)blocks, THREADS>>>(pred, targ, n_cells, n_full, out);
}